// round 1
// baseline (speedup 1.0000x reference)
#include <cuda_runtime.h>
#include <cstdint>

#define USER_NUM 100000
#define N_NODES  200000
#define EMB      64

// Scratch: two full node-embedding buffers (51.2 MB each). Static device
// globals — no allocation anywhere, graph-capture safe.
__device__ float g_buf_a[(size_t)N_NODES * EMB];
__device__ float g_buf_b[(size_t)N_NODES * EMB];
__device__ unsigned int g_is64;

// Detect whether the index arrays are int64 (all high 32-bit words zero over
// a large sample) or int32 (random values in [0, 200000) at odd word slots —
// probability of all-zero is negligible).
__global__ void detect_idx64(const unsigned int* __restrict__ p, int n_check) {
    __shared__ unsigned int s_acc;
    if (threadIdx.x == 0) s_acc = 0u;
    __syncthreads();
    unsigned int acc = 0u;
    for (int i = threadIdx.x; i < n_check; i += blockDim.x)
        acc |= p[2 * i + 1];
    atomicOr(&s_acc, acc);
    __syncthreads();
    if (threadIdx.x == 0) g_is64 = (s_acc == 0u) ? 1u : 0u;
}

__global__ void zero_kernel(float4* __restrict__ p, int n4) {
    int i = blockIdx.x * blockDim.x + threadIdx.x;
    int stride = gridDim.x * blockDim.x;
    float4 z = make_float4(0.f, 0.f, 0.f, 0.f);
    for (; i < n4; i += stride) p[i] = z;
}

// COO SpMM: 16 lanes per edge, float4 per lane (EMB=64).
// y[row[e]][:] += val[e] * x[col[e]][:]
// x is addressed as two halves (user/item) so layer 1 can read directly from
// the two input tensors; later layers pass buf and buf + USER_NUM*EMB.
__global__ void spmm_kernel(const void* __restrict__ rows,
                            const void* __restrict__ cols,
                            const float* __restrict__ val,
                            const float* __restrict__ x_user,
                            const float* __restrict__ x_item,
                            float* __restrict__ y,
                            int nnz) {
    long long t = (long long)blockIdx.x * blockDim.x + threadIdx.x;
    int e = (int)(t >> 4);
    if (e >= nnz) return;
    int sub = (int)(t & 15);

    int r, c;
    if (g_is64) {
        r = (int)((const long long*)rows)[e];
        c = (int)((const long long*)cols)[e];
    } else {
        r = ((const int*)rows)[e];
        c = ((const int*)cols)[e];
    }
    float v = __ldg(val + e);

    const float* xr = (c < USER_NUM) ? (x_user + (size_t)c * EMB)
                                     : (x_item + (size_t)(c - USER_NUM) * EMB);
    float4 xv = __ldg(((const float4*)xr) + sub);

    float* dst = y + (size_t)r * EMB + (size_t)sub * 4;
    asm volatile("red.global.add.v4.f32 [%0], {%1, %2, %3, %4};"
                 :: "l"(dst),
                    "f"(v * xv.x), "f"(v * xv.y), "f"(v * xv.z), "f"(v * xv.w)
                 : "memory");
}

// out = a
__global__ void copy_kernel(const float4* __restrict__ a,
                            float4* __restrict__ out, int n4) {
    int i = blockIdx.x * blockDim.x + threadIdx.x;
    int stride = gridDim.x * blockDim.x;
    for (; i < n4; i += stride) out[i] = a[i];
}

// out += b
__global__ void add_kernel(const float4* __restrict__ b,
                           float4* __restrict__ out, int n4) {
    int i = blockIdx.x * blockDim.x + threadIdx.x;
    int stride = gridDim.x * blockDim.x;
    for (; i < n4; i += stride) {
        float4 o = out[i];
        float4 v = b[i];
        o.x += v.x; o.y += v.y; o.z += v.z; o.w += v.w;
        out[i] = o;
    }
}

// out = (out + a) * (1/3)
__global__ void final_kernel(const float4* __restrict__ a,
                             float4* __restrict__ out, int n4) {
    const float s = 1.0f / 3.0f;
    int i = blockIdx.x * blockDim.x + threadIdx.x;
    int stride = gridDim.x * blockDim.x;
    for (; i < n4; i += stride) {
        float4 o = out[i];
        float4 v = a[i];
        o.x = (o.x + v.x) * s;
        o.y = (o.y + v.y) * s;
        o.z = (o.z + v.z) * s;
        o.w = (o.w + v.w) * s;
        out[i] = o;
    }
}

extern "C" void kernel_launch(void* const* d_in, const int* in_sizes, int n_in,
                              void* d_out, int out_size) {
    const float* user = (const float*)d_in[0];
    const float* item = (const float*)d_in[1];
    const void*  rows = d_in[2];
    const void*  cols = d_in[3];
    const float* val  = (const float*)d_in[4];
    int nnz = in_sizes[4];   // adj_val element count (dtype-independent)
    float* out = (float*)d_out;

    float* ba = nullptr;
    float* bb = nullptr;
    cudaGetSymbolAddress((void**)&ba, g_buf_a);
    cudaGetSymbolAddress((void**)&bb, g_buf_b);

    const int n4 = (N_NODES * EMB) / 4;
    long long lanes = (long long)nnz * 16;
    int sblocks = (int)((lanes + 255) / 256);

    int n_check = 4096;
    if (nnz / 2 < n_check) n_check = nnz / 2;
    detect_idx64<<<1, 256>>>((const unsigned int*)rows, n_check);

    // Layer 1: e1 = spmm(x0)  -> buf_a
    zero_kernel<<<1024, 256>>>((float4*)ba, n4);
    spmm_kernel<<<sblocks, 256>>>(rows, cols, val, user, item, ba, nnz);

    // acc = e1 ; Layer 2: e2 = spmm(e1) -> buf_b
    copy_kernel<<<1024, 256>>>((const float4*)ba, (float4*)out, n4);
    zero_kernel<<<1024, 256>>>((float4*)bb, n4);
    spmm_kernel<<<sblocks, 256>>>(rows, cols, val,
                                  ba, ba + (size_t)USER_NUM * EMB, bb, nnz);

    // acc += e2 ; Layer 3: e3 = spmm(e2) -> buf_a (re-zeroed)
    add_kernel<<<1024, 256>>>((const float4*)bb, (float4*)out, n4);
    zero_kernel<<<1024, 256>>>((float4*)ba, n4);
    spmm_kernel<<<sblocks, 256>>>(rows, cols, val,
                                  bb, bb + (size_t)USER_NUM * EMB, ba, nnz);

    // out = (acc + e3) / 3
    final_kernel<<<1024, 256>>>((const float4*)ba, (float4*)out, n4);
}

// round 2
// speedup vs baseline: 2.2404x; 2.2404x over previous
#include <cuda_runtime.h>
#include <cstdint>

#define USER_NUM 100000
#define N_NODES  200000
#define EMB      64
#define NNZ_MAX  4200000

#define SCAN_TPB 512
#define SCAN_BLOCKS ((N_NODES + SCAN_TPB - 1) / SCAN_TPB)   // 391

// ---- static device scratch (no allocation anywhere) ----
__device__ float g_buf_a[(size_t)N_NODES * EMB];            // 51.2 MB
__device__ float g_buf_b[(size_t)N_NODES * EMB];            // 51.2 MB
__device__ unsigned long long g_pairs[NNZ_MAX];             // 33.6 MB (val<<32 | col)
__device__ unsigned int g_cnt[N_NODES];
__device__ unsigned int g_rowptr[N_NODES + 1];
__device__ unsigned int g_rowcur[N_NODES];
__device__ unsigned int g_blocksum[SCAN_BLOCKS];
__device__ unsigned int g_is64;

// ---------------------------------------------------------------------------
// Zero the histogram counters; block 0 additionally detects int64 vs int32
// indices (high 32-bit words all zero over a sample => int64).
__global__ void init_kernel(const unsigned int* __restrict__ rows, int n_check) {
    int stride = gridDim.x * blockDim.x;
    for (int j = blockIdx.x * blockDim.x + threadIdx.x; j < N_NODES; j += stride)
        g_cnt[j] = 0u;
    if (blockIdx.x == 0) {
        __shared__ unsigned int s_acc;
        if (threadIdx.x == 0) s_acc = 0u;
        __syncthreads();
        unsigned int a = 0u;
        for (int j = threadIdx.x; j < n_check; j += blockDim.x)
            a |= rows[2 * j + 1];
        atomicOr(&s_acc, a);
        __syncthreads();
        if (threadIdx.x == 0) g_is64 = (s_acc == 0u) ? 1u : 0u;
    }
}

__device__ __forceinline__ int load_idx(const void* p, int e) {
    return g_is64 ? (int)((const long long*)p)[e] : ((const int*)p)[e];
}

// ---------------------------------------------------------------------------
__global__ void hist_kernel(const void* __restrict__ rows, int nnz) {
    int e = blockIdx.x * blockDim.x + threadIdx.x;
    if (e >= nnz) return;
    atomicAdd(&g_cnt[load_idx(rows, e)], 1u);
}

// Exclusive scan, 3 phases. Phase 1: per-block scan, write exclusive values
// and block totals.
__global__ void scan1_kernel() {
    __shared__ unsigned int s[SCAN_TPB];
    int i = blockIdx.x * SCAN_TPB + threadIdx.x;
    unsigned int v = (i < N_NODES) ? g_cnt[i] : 0u;
    s[threadIdx.x] = v;
    __syncthreads();
    for (int off = 1; off < SCAN_TPB; off <<= 1) {
        unsigned int t = (threadIdx.x >= off) ? s[threadIdx.x - off] : 0u;
        __syncthreads();
        s[threadIdx.x] += t;
        __syncthreads();
    }
    unsigned int incl = s[threadIdx.x];
    if (i < N_NODES) g_rowptr[i] = incl - v;          // block-local exclusive
    if (threadIdx.x == SCAN_TPB - 1) g_blocksum[blockIdx.x] = incl;
}

// Phase 2: exclusive scan of the block totals (single block).
__global__ void scan2_kernel() {
    __shared__ unsigned int s[SCAN_TPB];
    unsigned int v = (threadIdx.x < SCAN_BLOCKS) ? g_blocksum[threadIdx.x] : 0u;
    s[threadIdx.x] = v;
    __syncthreads();
    for (int off = 1; off < SCAN_TPB; off <<= 1) {
        unsigned int t = (threadIdx.x >= off) ? s[threadIdx.x - off] : 0u;
        __syncthreads();
        s[threadIdx.x] += t;
        __syncthreads();
    }
    if (threadIdx.x < SCAN_BLOCKS) g_blocksum[threadIdx.x] = s[threadIdx.x] - v;
}

// Phase 3: add block offsets; init scatter cursors; cap rowptr.
__global__ void scan3_kernel(int nnz) {
    int i = blockIdx.x * SCAN_TPB + threadIdx.x;
    if (i < N_NODES) {
        unsigned int p = g_rowptr[i] + g_blocksum[blockIdx.x];
        g_rowptr[i] = p;
        g_rowcur[i] = p;
    }
    if (i == 0) g_rowptr[N_NODES] = (unsigned int)nnz;
}

// Permute edges into row-sorted order as packed (val, col) 8-byte pairs.
__global__ void scatter_kernel(const void* __restrict__ rows,
                               const void* __restrict__ cols,
                               const float* __restrict__ val, int nnz) {
    int e = blockIdx.x * blockDim.x + threadIdx.x;
    if (e >= nnz) return;
    int r = load_idx(rows, e);
    int c = load_idx(cols, e);
    float v = __ldg(val + e);
    unsigned int pos = atomicAdd(&g_rowcur[r], 1u);
    g_pairs[pos] = ((unsigned long long)__float_as_uint(v) << 32) | (unsigned int)c;
}

// ---------------------------------------------------------------------------
// CSR SpMM: one warp per row. Lanes split into two 16-lane halves; each half
// processes alternate edges; lane (half,sub) owns float4 slice `sub` of the
// EMB=64 row. Register accumulation, shfl combine, single vector store.
// mode 0: ybuf = acc; out  = acc        (layer 1, fuses acc init)
// mode 1: ybuf = acc; out += acc        (layer 2, fuses acc add)
// mode 2:             out = (out+acc)/3 (layer 3, fuses final scale)
__global__ void spmm_csr_kernel(const float* __restrict__ x_user,
                                const float* __restrict__ x_item,
                                float* __restrict__ ybuf,
                                float* __restrict__ out,
                                int mode) {
    int row = blockIdx.x * (blockDim.x >> 5) + (threadIdx.x >> 5);
    if (row >= N_NODES) return;
    int lane = threadIdx.x & 31;
    int half = lane >> 4;
    int sub  = lane & 15;

    unsigned int beg = g_rowptr[row];
    unsigned int end = g_rowptr[row + 1];

    float4 acc = make_float4(0.f, 0.f, 0.f, 0.f);
    for (unsigned int e = beg + half; e < end; e += 2) {
        unsigned long long p = __ldcs(g_pairs + e);          // streaming
        int   c = (int)(unsigned int)p;
        float v = __uint_as_float((unsigned int)(p >> 32));
        const float4* xr = (c < USER_NUM)
            ? (const float4*)(x_user + (size_t)c * EMB)
            : (const float4*)(x_item + (size_t)(c - USER_NUM) * EMB);
        float4 xv = __ldg(xr + sub);
        acc.x += v * xv.x; acc.y += v * xv.y;
        acc.z += v * xv.z; acc.w += v * xv.w;
    }

    // combine the two halves (lane i += lane i^16)
    acc.x += __shfl_xor_sync(0xffffffffu, acc.x, 16);
    acc.y += __shfl_xor_sync(0xffffffffu, acc.y, 16);
    acc.z += __shfl_xor_sync(0xffffffffu, acc.z, 16);
    acc.w += __shfl_xor_sync(0xffffffffu, acc.w, 16);

    if (half == 0) {
        size_t o4 = (size_t)row * (EMB / 4) + sub;
        if (mode == 0) {
            ((float4*)ybuf)[o4] = acc;
            ((float4*)out)[o4]  = acc;
        } else if (mode == 1) {
            ((float4*)ybuf)[o4] = acc;
            float4 t = ((float4*)out)[o4];
            t.x += acc.x; t.y += acc.y; t.z += acc.z; t.w += acc.w;
            ((float4*)out)[o4] = t;
        } else {
            const float s = 1.0f / 3.0f;
            float4 t = ((float4*)out)[o4];
            t.x = (t.x + acc.x) * s; t.y = (t.y + acc.y) * s;
            t.z = (t.z + acc.z) * s; t.w = (t.w + acc.w) * s;
            ((float4*)out)[o4] = t;
        }
    }
}

// ---------------------------------------------------------------------------
extern "C" void kernel_launch(void* const* d_in, const int* in_sizes, int n_in,
                              void* d_out, int out_size) {
    const float* user = (const float*)d_in[0];
    const float* item = (const float*)d_in[1];
    const void*  rows = d_in[2];
    const void*  cols = d_in[3];
    const float* val  = (const float*)d_in[4];
    int nnz = in_sizes[4];                 // adj_val count (dtype-independent)
    float* out = (float*)d_out;

    float* ba = nullptr;
    float* bb = nullptr;
    cudaGetSymbolAddress((void**)&ba, g_buf_a);
    cudaGetSymbolAddress((void**)&bb, g_buf_b);

    int n_check = 4096;
    if (nnz / 2 < n_check) n_check = nnz / 2;

    int eblocks = (nnz + 255) / 256;
    int rblocks = (N_NODES + 7) / 8;       // 8 warps (rows) per 256-thread block

    // Build CSR (once per call; reused by all 3 layers)
    init_kernel<<<256, 256>>>((const unsigned int*)rows, n_check);
    hist_kernel<<<eblocks, 256>>>(rows, nnz);
    scan1_kernel<<<SCAN_BLOCKS, SCAN_TPB>>>();
    scan2_kernel<<<1, SCAN_TPB>>>();
    scan3_kernel<<<SCAN_BLOCKS, SCAN_TPB>>>(nnz);
    scatter_kernel<<<eblocks, 256>>>(rows, cols, val, nnz);

    // Layer 1: e1 = A x0 -> buf_a; out = e1
    spmm_csr_kernel<<<rblocks, 256>>>(user, item, ba, out, 0);
    // Layer 2: e2 = A e1 -> buf_b; out += e2
    spmm_csr_kernel<<<rblocks, 256>>>(ba, ba + (size_t)USER_NUM * EMB, bb, out, 1);
    // Layer 3: e3 = A e2; out = (out + e3) / 3
    spmm_csr_kernel<<<rblocks, 256>>>(bb, bb + (size_t)USER_NUM * EMB, ba, out, 2);
}